// round 13
// baseline (speedup 1.0000x reference)
#include <cuda_runtime.h>
#include <cuda_bf16.h>
#include <math.h>
#include <stdint.h>
#include <string.h>

typedef unsigned int u32;

// ---------------- problem constants ----------------
constexpr int BS  = 8;
constexpr int C   = 128;
constexpr int HH  = 128;
constexpr int WW  = 128;
constexpr int P   = HH * WW;
constexpr long long M = (long long)BS * P;  // 131072 rows
constexpr int HID = 512;

// ---------------- device scratch ----------------
__device__ float          g_xt  [(size_t)M * C];
__device__ __nv_bfloat16  g_qkvb[(size_t)M * 3 * C];
__device__ __nv_bfloat16  g_abuf[(size_t)M * C];
__device__ float          g_xt2 [(size_t)M * C];
__device__ __nv_bfloat16  g_h   [(size_t)M * HID];

// transposed bf16 weights [N][K]
__device__ __nv_bfloat16  g_wqkv_t[384 * 128];
__device__ __nv_bfloat16  g_proj_t[128 * 128];
__device__ __nv_bfloat16  g_fc1_t [512 * 128];
__device__ __nv_bfloat16  g_fc2_t [128 * 512];

// =================================================================
// primitives
// =================================================================
__device__ __forceinline__ void ldsm_x4(u32 &r0, u32 &r1, u32 &r2, u32 &r3, u32 addr)
{
    asm volatile("ldmatrix.sync.aligned.m8n8.x4.shared.b16 {%0,%1,%2,%3}, [%4];"
                 : "=r"(r0), "=r"(r1), "=r"(r2), "=r"(r3) : "r"(addr));
}
__device__ __forceinline__ void ldsm_x4_t(u32 &r0, u32 &r1, u32 &r2, u32 &r3, u32 addr)
{
    asm volatile("ldmatrix.sync.aligned.m8n8.x4.trans.shared.b16 {%0,%1,%2,%3}, [%4];"
                 : "=r"(r0), "=r"(r1), "=r"(r2), "=r"(r3) : "r"(addr));
}
__device__ __forceinline__ void mma_bf16(float* d, const u32* a, const u32* b)
{
    asm volatile("mma.sync.aligned.m16n8k16.row.col.f32.bf16.bf16.f32 "
                 "{%0,%1,%2,%3}, {%4,%5,%6,%7}, {%8,%9}, {%0,%1,%2,%3};"
                 : "+f"(d[0]), "+f"(d[1]), "+f"(d[2]), "+f"(d[3])
                 : "r"(a[0]), "r"(a[1]), "r"(a[2]), "r"(a[3]),
                   "r"(b[0]), "r"(b[1]));
}
__device__ __forceinline__ u32 pack_bf16x2(float a, float b)
{
    __nv_bfloat162 t = __floats2bfloat162_rn(a, b);
    u32 r;
    memcpy(&r, &t, 4);
    return r;
}
__device__ __forceinline__ float ex2(float x)
{
    float r;
    asm("ex2.approx.f32 %0, %1;" : "=f"(r) : "f"(x));
    return r;
}
__device__ __forceinline__ void cp16(u32 dst, const void* src)
{
    asm volatile("cp.async.cg.shared.global [%0], [%1], 16;" :: "r"(dst), "l"(src));
}
__device__ __forceinline__ void cp_commit()
{
    asm volatile("cp.async.commit_group;");
}
template <int N>
__device__ __forceinline__ void cp_wait()
{
    asm volatile("cp.async.wait_group %0;" :: "n"(N));
}

constexpr int ASTR = 136;    // resident A row stride (bf16)
constexpr int BST64 = 72;    // BK=64 staged tile row stride
constexpr int LDS_S = 40;    // BK=32 staged tile row stride

// =================================================================
// merged weight transpose + bf16 convert
// =================================================================
__global__ void wt_all_kernel(const float* __restrict__ wqkv, const float* __restrict__ projw,
                              const float* __restrict__ fc1w, const float* __restrict__ fc2w,
                              __nv_bfloat16* oq, __nv_bfloat16* op,
                              __nv_bfloat16* o1, __nv_bfloat16* o2)
{
    __shared__ float t[32][33];
    int id = blockIdx.x;
    const float* W; __nv_bfloat16* Wt; int K, N, local;
    if (id < 48)       { W = wqkv;  Wt = oq; K = 128; N = 384; local = id; }
    else if (id < 64)  { W = projw; Wt = op; K = 128; N = 128; local = id - 48; }
    else if (id < 128) { W = fc1w;  Wt = o1; K = 128; N = 512; local = id - 64; }
    else               { W = fc2w;  Wt = o2; K = 512; N = 128; local = id - 128; }
    int nTiles = N / 32;
    int n0 = (local % nTiles) * 32;
    int k0 = (local / nTiles) * 32;
    int tx = threadIdx.x, ty = threadIdx.y;
    for (int i = ty; i < 32; i += 8)
        t[i][tx] = W[(size_t)(k0 + i) * N + n0 + tx];
    __syncthreads();
    for (int i = ty; i < 32; i += 8)
        Wt[(size_t)(n0 + i) * K + k0 + tx] = __float2bfloat16(t[tx][i]);
}

// =================================================================
// depthwise 3x3 conv + bias + residual -> xt (B,P,C)
// =================================================================
__global__ __launch_bounds__(256) void conv_kernel(
    const float* __restrict__ x, const float* __restrict__ cw,
    const float* __restrict__ cb, float* __restrict__ xt)
{
    int b  = blockIdx.z;
    int h  = blockIdx.y;
    int c0 = (blockIdx.x >> 2) * 32;
    int w0 = (blockIdx.x & 3) * 32;
    __shared__ float sx[32][3][36];
    __shared__ float so[32][33];
    int tid = threadIdx.x;

    for (int i = tid; i < 32 * 3 * 34; i += 256) {
        int c  = i / (3 * 34);
        int r  = (i / 34) % 3;
        int wi = i % 34;
        int hh = h + r - 1;
        int wg = w0 + wi - 1;
        float v = 0.f;
        if (hh >= 0 && hh < HH && wg >= 0 && wg < WW)
            v = x[(((size_t)b * C + c0 + c) * HH + hh) * WW + wg];
        sx[c][r][wi] = v;
    }
    __syncthreads();

    int c     = tid >> 3;
    int wbase = (tid & 7) * 4;
    const float* wg9 = cw + (size_t)(c0 + c) * 9;
    float w00 = wg9[0], w01 = wg9[1], w02 = wg9[2];
    float w10 = wg9[3], w11 = wg9[4], w12 = wg9[5];
    float w20 = wg9[6], w21 = wg9[7], w22 = wg9[8];
    float bias = cb[c0 + c];
#pragma unroll
    for (int j = 0; j < 4; j++) {
        int wi = wbase + j;
        float acc = sx[c][0][wi] * w00 + sx[c][0][wi+1] * w01 + sx[c][0][wi+2] * w02
                  + sx[c][1][wi] * w10 + sx[c][1][wi+1] * w11 + sx[c][1][wi+2] * w12
                  + sx[c][2][wi] * w20 + sx[c][2][wi+1] * w21 + sx[c][2][wi+2] * w22;
        so[c][wi] = acc + bias + sx[c][1][wi+1];
    }
    __syncthreads();

    int cc = tid & 31;
    for (int wr = tid >> 5; wr < 32; wr += 8) {
        xt[((size_t)b * P + (size_t)h * WW + w0 + wr) * C + c0 + cc] = so[cc][wr];
    }
}

// =================================================================
// Epilogue functor (QKV)
// =================================================================
struct EpiQKVb {
    __nv_bfloat16* out;
    __device__ __forceinline__ void store(size_t row, int col, float2 v) const {
        *(__nv_bfloat162*)(out + row * 384 + col) = __floats2bfloat162_rn(v.x, v.y);
    }
};

// =================================================================
// Fused LN + GEMM, K=128, BK=64, B via 3-stage cp.async. (QKV)
// =================================================================
template <int NCB, class Epi>
__global__ __launch_bounds__(256, 2) void lngemm_kernel(
    const float* __restrict__ A, const float* __restrict__ lnw,
    const float* __restrict__ lnb, const __nv_bfloat16* __restrict__ Bw,
    Epi epi)
{
    __shared__ __align__(16) __nv_bfloat16 As[128][ASTR];
    __shared__ __align__(16) __nv_bfloat16 Bs[3][128][BST64];
    int tid = threadIdx.x, lane = tid & 31, w = tid >> 5;
    int wm = w & 1, wn = w >> 1;
    size_t rowBase = (size_t)blockIdx.x * 128;

    int ldRow = tid >> 1, ldHalf = tid & 1;
    u32 sBbase = (u32)__cvta_generic_to_shared(&Bs[0][0][0]);
    constexpr u32 SLOT = 128 * BST64 * 2;
    constexpr int S = NCB * 2;

    auto issueB = [&](int t, int slot) {
        int cb = t >> 1, s = t & 1;
        const __nv_bfloat16* src = Bw + (size_t)(cb * 128 + ldRow) * 128
                                      + s * 64 + ldHalf * 32;
        u32 dst = sBbase + slot * SLOT + (u32)((ldRow * BST64 + ldHalf * 32) * 2);
#pragma unroll
        for (int j = 0; j < 4; j++) cp16(dst + j * 16, src + j * 8);
    };

    issueB(0, 0); cp_commit();
    issueB(1, 1); cp_commit();

    // ---- LN (once) ----
    {
        int row = tid >> 1, half = tid & 1;
        const float4* src = (const float4*)(A + (rowBase + row) * 128 + half * 64);
        float s = 0.f, q = 0.f;
#pragma unroll
        for (int i = 0; i < 16; i++) {
            float4 v = src[i];
            s += v.x + v.y + v.z + v.w;
            q += v.x*v.x + v.y*v.y + v.z*v.z + v.w*v.w;
        }
        s += __shfl_xor_sync(0xffffffffu, s, 1);
        q += __shfl_xor_sync(0xffffffffu, q, 1);
        float mean = s * (1.f / 128.f);
        float var  = q * (1.f / 128.f) - mean * mean;
        float rstd = rsqrtf(var + 1e-5f);
        const float4* wp = (const float4*)(lnw + half * 64);
        const float4* bp = (const float4*)(lnb + half * 64);
#pragma unroll
        for (int j = 0; j < 8; j++) {
            float4 a  = src[2*j],  b2  = src[2*j+1];
            float4 w4 = wp[2*j],   w42 = wp[2*j+1];
            float4 b4 = bp[2*j],   b42 = bp[2*j+1];
            u32 o[4];
            o[0] = pack_bf16x2((a.x-mean)*rstd*w4.x + b4.x,  (a.y-mean)*rstd*w4.y + b4.y);
            o[1] = pack_bf16x2((a.z-mean)*rstd*w4.z + b4.z,  (a.w-mean)*rstd*w4.w + b4.w);
            o[2] = pack_bf16x2((b2.x-mean)*rstd*w42.x + b42.x,(b2.y-mean)*rstd*w42.y + b42.y);
            o[3] = pack_bf16x2((b2.z-mean)*rstd*w42.z + b42.z,(b2.w-mean)*rstd*w42.w + b42.w);
            *(uint4*)&As[row][half * 64 + j * 8] = *(uint4*)o;
        }
    }

    u32 sA = (u32)__cvta_generic_to_shared(&As[0][0]);
    int arow = wm * 64 + (lane & 15);
    int brow = wn * 32 + (lane & 15);
    int csel = (lane >> 4) * 8;

    float acc[4][4][4];
#pragma unroll
    for (int t = 0; t < S; t++) {
        cp_wait<1>();
        __syncthreads();
        if (t + 2 < S) issueB(t + 2, (t + 2) % 3);
        cp_commit();

        if ((t & 1) == 0) {
#pragma unroll
            for (int i = 0; i < 4; i++)
#pragma unroll
                for (int j = 0; j < 4; j++)
#pragma unroll
                    for (int r = 0; r < 4; r++) acc[i][j][r] = 0.f;
        }
        u32 sB = sBbase + (u32)((t % 3) * SLOT);
#pragma unroll
        for (int kk = 0; kk < 4; kk++) {
            int acol = (t & 1) * 64 + kk * 16 + csel;
            int bcol = kk * 16 + csel;
            u32 af[4][4], bf[4][2];
#pragma unroll
            for (int mi = 0; mi < 4; mi++) {
                u32 addr = sA + (u32)(((arow + mi * 16) * ASTR + acol) * 2);
                ldsm_x4(af[mi][0], af[mi][1], af[mi][2], af[mi][3], addr);
            }
#pragma unroll
            for (int np = 0; np < 2; np++) {
                u32 r0, r1, r2, r3;
                u32 addr = sB + (u32)(((brow + np * 16) * BST64 + bcol) * 2);
                ldsm_x4(r0, r1, r2, r3, addr);
                bf[np * 2][0]     = r0; bf[np * 2][1]     = r2;
                bf[np * 2 + 1][0] = r1; bf[np * 2 + 1][1] = r3;
            }
#pragma unroll
            for (int mi = 0; mi < 4; mi++)
#pragma unroll
                for (int nj = 0; nj < 4; nj++)
                    mma_bf16(acc[mi][nj], af[mi], bf[nj]);
        }
        if ((t & 1) == 1) {
            int colBase = (t >> 1) * 128;
#pragma unroll
            for (int mi = 0; mi < 4; mi++)
#pragma unroll
                for (int rp = 0; rp < 2; rp++) {
                    size_t r = rowBase + wm * 64 + mi * 16 + rp * 8 + (lane >> 2);
#pragma unroll
                    for (int nj = 0; nj < 4; nj++) {
                        int cgl = colBase + wn * 32 + nj * 8 + (lane & 3) * 2;
                        epi.store(r, cgl, make_float2(acc[mi][nj][rp * 2],
                                                      acc[mi][nj][rp * 2 + 1]));
                    }
                }
        }
    }
}

// =================================================================
// FUSED proj GEMM (K=128) + ls1-residual -> xt2 + LN2 + FC1 GEMM
// (+bias+GELU -> h). grid (M/128), 256 thr.
// smem pool aliases proj staging (3x2 slots, 60KB) with fc1 B
// staging (3 slots, 54KB); resident LN'd A separate (34KB).
// =================================================================
__global__ __launch_bounds__(256, 2) void projln_fc1_kernel(
    const __nv_bfloat16* __restrict__ Aab, const __nv_bfloat16* __restrict__ Bproj,
    const float* __restrict__ pbias, const float* __restrict__ ls,
    const float* __restrict__ xt, float* __restrict__ xt2,
    const float* __restrict__ lnw, const float* __restrict__ lnb,
    const __nv_bfloat16* __restrict__ Bfc1, const float* __restrict__ fbias,
    __nv_bfloat16* __restrict__ hout)
{
    __shared__ __align__(16) char pool[3 * 128 * LDS_S * 2 * 2];   // 61440 B
    __shared__ __align__(16) __nv_bfloat16 As[128][ASTR];          // 34816 B
    int tid = threadIdx.x, lane = tid & 31, w = tid >> 5;
    int wm = w & 1, wn = w >> 1;
    size_t rowBase = (size_t)blockIdx.x * 128;

    int ldRow = tid >> 1, ldHalf = tid & 1;
    u32 poolBase = (u32)__cvta_generic_to_shared(pool);
    constexpr u32 PSLOT = 128 * LDS_S * 2;       // 10240
    u32 pA = poolBase, pB = poolBase + 3 * PSLOT;
    u32 dstOff32 = (u32)((ldRow * LDS_S + ldHalf * 16) * 2);

    int arow = wm * 64 + (lane & 15);
    int brow = wn * 32 + (lane & 15);
    int csel = (lane >> 4) * 8;
    u32 sAres = (u32)__cvta_generic_to_shared(&As[0][0]);

    float acc[4][4][4];

    // ============ PHASE 1: proj GEMM (K=128, 4 stages, 3 slots) =====
    {
        const __nv_bfloat16* Arow = Aab + (rowBase + ldRow) * 128 + ldHalf * 16;
        const __nv_bfloat16* Brow = Bproj + (size_t)ldRow * 128 + ldHalf * 16;
        auto issue = [&](int t, int slot) {
            const __nv_bfloat16* sa = Arow + t * 32;
            const __nv_bfloat16* sb = Brow + t * 32;
            u32 da = pA + slot * PSLOT + dstOff32;
            u32 db = pB + slot * PSLOT + dstOff32;
            cp16(da, sa); cp16(da + 16, sa + 8);
            cp16(db, sb); cp16(db + 16, sb + 8);
        };
        issue(0, 0); cp_commit();
        issue(1, 1); cp_commit();

#pragma unroll
        for (int i = 0; i < 4; i++)
#pragma unroll
            for (int j = 0; j < 4; j++)
#pragma unroll
                for (int r = 0; r < 4; r++) acc[i][j][r] = 0.f;

#pragma unroll
        for (int t = 0; t < 4; t++) {
            cp_wait<1>();
            __syncthreads();
            if (t + 2 < 4) issue(t + 2, (t + 2) % 3);
            cp_commit();
            u32 sA = pA + (u32)((t % 3) * PSLOT);
            u32 sB = pB + (u32)((t % 3) * PSLOT);
#pragma unroll
            for (int kk = 0; kk < 32; kk += 16) {
                u32 af[4][4], bf[4][2];
                int acol = kk + csel;
#pragma unroll
                for (int mi = 0; mi < 4; mi++) {
                    u32 addr = sA + (u32)(((arow + mi * 16) * LDS_S + acol) * 2);
                    ldsm_x4(af[mi][0], af[mi][1], af[mi][2], af[mi][3], addr);
                }
#pragma unroll
                for (int np = 0; np < 2; np++) {
                    u32 r0, r1, r2, r3;
                    u32 addr = sB + (u32)(((brow + np * 16) * LDS_S + acol) * 2);
                    ldsm_x4(r0, r1, r2, r3, addr);
                    bf[np * 2][0]     = r0; bf[np * 2][1]     = r2;
                    bf[np * 2 + 1][0] = r1; bf[np * 2 + 1][1] = r3;
                }
#pragma unroll
                for (int mi = 0; mi < 4; mi++)
#pragma unroll
                    for (int nj = 0; nj < 4; nj++)
                        mma_bf16(acc[mi][nj], af[mi], bf[nj]);
            }
        }
    }

    // ---- proj epilogue: xt2 = xt + ls1*(acc+bias)  (global write) ----
#pragma unroll
    for (int mi = 0; mi < 4; mi++)
#pragma unroll
        for (int rp = 0; rp < 2; rp++) {
            size_t r = rowBase + wm * 64 + mi * 16 + rp * 8 + (lane >> 2);
#pragma unroll
            for (int nj = 0; nj < 4; nj++) {
                int col = wn * 32 + nj * 8 + (lane & 3) * 2;
                float2 bb = *(const float2*)(pbias + col);
                float2 ss = *(const float2*)(ls + col);
                float2 rr = *(const float2*)(xt + r * 128 + col);
                float2 o;
                o.x = rr.x + ss.x * (acc[mi][nj][rp*2]   + bb.x);
                o.y = rr.y + ss.y * (acc[mi][nj][rp*2+1] + bb.y);
                *(float2*)(xt2 + r * 128 + col) = o;
            }
        }
    cp_wait<0>();
    __syncthreads();   // xt2 of this CTA's rows visible to all its threads

    // ============ PHASE 2: fc1 B staging + LN2 on xt2 ===============
    constexpr u32 BSLOT = 128 * BST64 * 2;     // 18432; 3 slots fit in pool
    auto issueB = [&](int t, int slot) {
        int cb = t >> 1, s = t & 1;
        const __nv_bfloat16* src = Bfc1 + (size_t)(cb * 128 + ldRow) * 128
                                       + s * 64 + ldHalf * 32;
        u32 dst = poolBase + slot * BSLOT + (u32)((ldRow * BST64 + ldHalf * 32) * 2);
#pragma unroll
        for (int j = 0; j < 4; j++) cp16(dst + j * 16, src + j * 8);
    };
    issueB(0, 0); cp_commit();
    issueB(1, 1); cp_commit();

    {
        int row = tid >> 1, half = tid & 1;
        const float4* src = (const float4*)(xt2 + (rowBase + row) * 128 + half * 64);
        float s = 0.f, q = 0.f;
#pragma unroll
        for (int i = 0; i < 16; i++) {
            float4 v = src[i];
            s += v.x + v.y + v.z + v.w;
            q += v.x*v.x + v.y*v.y + v.z*v.z + v.w*v.w;
        }
        s += __shfl_xor_sync(0xffffffffu, s, 1);
        q += __shfl_xor_sync(0xffffffffu, q, 1);
        float mean = s * (1.f / 128.f);
        float var  = q * (1.f / 128.f) - mean * mean;
        float rstd = rsqrtf(var + 1e-5f);
        const float4* wp = (const float4*)(lnw + half * 64);
        const float4* bp = (const float4*)(lnb + half * 64);
#pragma unroll
        for (int j = 0; j < 8; j++) {
            float4 a  = src[2*j],  b2  = src[2*j+1];
            float4 w4 = wp[2*j],   w42 = wp[2*j+1];
            float4 b4 = bp[2*j],   b42 = bp[2*j+1];
            u32 o[4];
            o[0] = pack_bf16x2((a.x-mean)*rstd*w4.x + b4.x,  (a.y-mean)*rstd*w4.y + b4.y);
            o[1] = pack_bf16x2((a.z-mean)*rstd*w4.z + b4.z,  (a.w-mean)*rstd*w4.w + b4.w);
            o[2] = pack_bf16x2((b2.x-mean)*rstd*w42.x + b42.x,(b2.y-mean)*rstd*w42.y + b42.y);
            o[3] = pack_bf16x2((b2.z-mean)*rstd*w42.z + b42.z,(b2.w-mean)*rstd*w42.w + b42.w);
            *(uint4*)&As[row][half * 64 + j * 8] = *(uint4*)o;
        }
    }

    // ============ PHASE 3: fc1 GEMM (4 column blocks, BK=64) ========
    constexpr int S = 8;   // 4 blocks * 2 stages
#pragma unroll
    for (int t = 0; t < S; t++) {
        cp_wait<1>();
        __syncthreads();
        if (t + 2 < S) issueB(t + 2, (t + 2) % 3);
        cp_commit();

        if ((t & 1) == 0) {
#pragma unroll
            for (int i = 0; i < 4; i++)
#pragma unroll
                for (int j = 0; j < 4; j++)
#pragma unroll
                    for (int r = 0; r < 4; r++) acc[i][j][r] = 0.f;
        }
        u32 sB = poolBase + (u32)((t % 3) * BSLOT);
#pragma unroll
        for (int kk = 0; kk < 4; kk++) {
            int acol = (t & 1) * 64 + kk * 16 + csel;
            int bcol = kk * 16 + csel;
            u32 af[4][4], bf[4][2];
#pragma unroll
            for (int mi = 0; mi < 4; mi++) {
                u32 addr = sAres + (u32)(((arow + mi * 16) * ASTR + acol) * 2);
                ldsm_x4(af[mi][0], af[mi][1], af[mi][2], af[mi][3], addr);
            }
#pragma unroll
            for (int np = 0; np < 2; np++) {
                u32 r0, r1, r2, r3;
                u32 addr = sB + (u32)(((brow + np * 16) * BST64 + bcol) * 2);
                ldsm_x4(r0, r1, r2, r3, addr);
                bf[np * 2][0]     = r0; bf[np * 2][1]     = r2;
                bf[np * 2 + 1][0] = r1; bf[np * 2 + 1][1] = r3;
            }
#pragma unroll
            for (int mi = 0; mi < 4; mi++)
#pragma unroll
                for (int nj = 0; nj < 4; nj++)
                    mma_bf16(acc[mi][nj], af[mi], bf[nj]);
        }
        if ((t & 1) == 1) {
            int colBase = (t >> 1) * 128;
#pragma unroll
            for (int mi = 0; mi < 4; mi++)
#pragma unroll
                for (int rp = 0; rp < 2; rp++) {
                    size_t r = rowBase + wm * 64 + mi * 16 + rp * 8 + (lane >> 2);
#pragma unroll
                    for (int nj = 0; nj < 4; nj++) {
                        int cgl = colBase + wn * 32 + nj * 8 + (lane & 3) * 2;
                        float2 bb = *(const float2*)(fbias + cgl);
                        float g0 = acc[mi][nj][rp*2]   + bb.x;
                        float g1 = acc[mi][nj][rp*2+1] + bb.y;
                        g0 = 0.5f * g0 * (1.f + erff(g0 * 0.70710678118654752f));
                        g1 = 0.5f * g1 * (1.f + erff(g1 * 0.70710678118654752f));
                        *(__nv_bfloat162*)(hout + r * 512 + cgl) =
                            __floats2bfloat162_rn(g0, g1);
                    }
                }
        }
    }
}

// =================================================================
// FC2 GEMM (K=512, BK=32, 4-stage cp.async) + bias + ls2 + residual
// + TRANSPOSED store to d_out (B,C,P).
// =================================================================
__global__ __launch_bounds__(256, 2) void bgemm_fc2_tr_kernel(
    const __nv_bfloat16* __restrict__ A, const __nv_bfloat16* __restrict__ Bw,
    const float* __restrict__ bias, const float* __restrict__ ls,
    const float* __restrict__ resid, float* __restrict__ out)
{
    __shared__ __align__(16) __nv_bfloat16 As[4][128][LDS_S];
    __shared__ __align__(16) __nv_bfloat16 Bs[4][128][LDS_S];
    __shared__ float tsm[32][132];
    constexpr int K = 512;
    constexpr int S = K >> 5;
    int tid = threadIdx.x, lane = tid & 31, w = tid >> 5;
    int wm = w & 1, wn = w >> 1;
    size_t rowBase = (size_t)blockIdx.y * 128;

    int ldRow = tid >> 1, ldHalf = tid & 1;
    u32 sAbase = (u32)__cvta_generic_to_shared(&As[0][0][0]);
    u32 sBbase = (u32)__cvta_generic_to_shared(&Bs[0][0][0]);
    constexpr u32 SLOT = 128 * LDS_S * 2;
    const __nv_bfloat16* Arow = A  + (rowBase + ldRow) * K + ldHalf * 16;
    const __nv_bfloat16* Brow = Bw + (size_t)ldRow * K + ldHalf * 16;
    u32 dstOff = (u32)((ldRow * LDS_S + ldHalf * 16) * 2);

    auto issue = [&](int t, int slot) {
        const __nv_bfloat16* sa = Arow + t * 32;
        const __nv_bfloat16* sb = Brow + t * 32;
        u32 da = sAbase + slot * SLOT + dstOff;
        u32 db = sBbase + slot * SLOT + dstOff;
        cp16(da, sa); cp16(da + 16, sa + 8);
        cp16(db, sb); cp16(db + 16, sb + 8);
    };

    issue(0, 0); cp_commit();
    issue(1, 1); cp_commit();
    issue(2, 2); cp_commit();

    float acc[4][4][4];
#pragma unroll
    for (int i = 0; i < 4; i++)
#pragma unroll
        for (int j = 0; j < 4; j++)
#pragma unroll
            for (int r = 0; r < 4; r++) acc[i][j][r] = 0.f;

    int arow = wm * 64 + (lane & 15);
    int brow = wn * 32 + (lane & 15);
    int csel = (lane >> 4) * 8;

    for (int t = 0; t < S; t++) {
        cp_wait<2>();
        __syncthreads();
        if (t + 3 < S) issue(t + 3, (t + 3) & 3);
        cp_commit();

        u32 sA = sAbase + (u32)((t & 3) * SLOT);
        u32 sB = sBbase + (u32)((t & 3) * SLOT);
#pragma unroll
        for (int kk = 0; kk < 32; kk += 16) {
            u32 af[4][4], bf[4][2];
            int acol = kk + csel;
#pragma unroll
            for (int mi = 0; mi < 4; mi++) {
                u32 addr = sA + (u32)(((arow + mi * 16) * LDS_S + acol) * 2);
                ldsm_x4(af[mi][0], af[mi][1], af[mi][2], af[mi][3], addr);
            }
#pragma unroll
            for (int np = 0; np < 2; np++) {
                u32 r0, r1, r2, r3;
                u32 addr = sB + (u32)(((brow + np * 16) * LDS_S + acol) * 2);
                ldsm_x4(r0, r1, r2, r3, addr);
                bf[np * 2][0]     = r0; bf[np * 2][1]     = r2;
                bf[np * 2 + 1][0] = r1; bf[np * 2 + 1][1] = r3;
            }
#pragma unroll
            for (int mi = 0; mi < 4; mi++)
#pragma unroll
                for (int nj = 0; nj < 4; nj++)
                    mma_bf16(acc[mi][nj], af[mi], bf[nj]);
        }
    }

    int b  = (int)(rowBase / P);
    int p0 = (int)(rowBase % P);
#pragma unroll
    for (int cg = 0; cg < 4; cg++) {
        __syncthreads();
        if (wn == cg) {
#pragma unroll
            for (int mi = 0; mi < 4; mi++)
#pragma unroll
                for (int rp = 0; rp < 2; rp++) {
                    int pl = wm * 64 + mi * 16 + rp * 8 + (lane >> 2);
                    size_t grow = rowBase + pl;
#pragma unroll
                    for (int nj = 0; nj < 4; nj++) {
                        int cl = nj * 8 + (lane & 3) * 2;
                        int cglob = cg * 32 + cl;
                        float2 bb = *(const float2*)(bias + cglob);
                        float2 ss = *(const float2*)(ls + cglob);
                        float2 rr = *(const float2*)(resid + grow * 128 + cglob);
                        tsm[cl][pl]     = rr.x + ss.x * (acc[mi][nj][rp*2]   + bb.x);
                        tsm[cl + 1][pl] = rr.y + ss.y * (acc[mi][nj][rp*2+1] + bb.y);
                    }
                }
        }
        __syncthreads();
        int c  = tid >> 3;
        int pj = (tid & 7) * 16;
        float* dst = out + (size_t)b * C * P + (size_t)(cg * 32 + c) * P + p0 + pj;
        const float* srcp = &tsm[c][pj];
#pragma unroll
        for (int j = 0; j < 4; j++)
            *(float4*)(dst + j * 4) = *(const float4*)(srcp + j * 4);
    }
}

// =================================================================
// Warp-level attention core
// =================================================================
constexpr int AST = 24;

__device__ __forceinline__ void attn_warp(
    const __nv_bfloat16* Qs, const __nv_bfloat16* Ks, const __nv_bfloat16* Vs,
    int nchunks, int lane, float o[2][2][4], float rsum[2][2])
{
    const float c2 = 0.25f * 1.4426950408889634f;   // scale * log2(e)
    int g = lane >> 3, i = lane & 7;
    int r4 = lane >> 2, c4 = lane & 3;

    u32 aq[2][4];
#pragma unroll
    for (int mt = 0; mt < 2; mt++) {
        u32 addr = (u32)__cvta_generic_to_shared(
            Qs + (mt * 16 + (g & 1) * 8 + i) * AST + (g >> 1) * 8);
        ldsm_x4(aq[mt][0], aq[mt][1], aq[mt][2], aq[mt][3], addr);
    }

#pragma unroll
    for (int mt = 0; mt < 2; mt++)
#pragma unroll
        for (int nh = 0; nh < 2; nh++)
#pragma unroll
            for (int q = 0; q < 4; q++) o[mt][nh][q] = 0.f;
    rsum[0][0] = rsum[0][1] = rsum[1][0] = rsum[1][1] = 0.f;

    for (int ch = 0; ch < nchunks; ch++) {
        const __nv_bfloat16* Kc = Ks + ch * 64 * AST;
        const __nv_bfloat16* Vc = Vs + ch * 64 * AST;
        u32 pf[2][4][4];
#pragma unroll
        for (int nt = 0; nt < 8; nt++) {
            const __nv_bfloat16* kp = Kc + (nt * 8 + r4) * AST + c4 * 2;
            u32 bb[2];
            bb[0] = *(const u32*)kp;
            bb[1] = *(const u32*)(kp + 8);
            float s0[4] = {0.f, 0.f, 0.f, 0.f};
            float s1[4] = {0.f, 0.f, 0.f, 0.f};
            mma_bf16(s0, aq[0], bb);
            mma_bf16(s1, aq[1], bb);
            float e00 = ex2(s0[0] * c2), e01 = ex2(s0[1] * c2);
            float e02 = ex2(s0[2] * c2), e03 = ex2(s0[3] * c2);
            float e10 = ex2(s1[0] * c2), e11 = ex2(s1[1] * c2);
            float e12 = ex2(s1[2] * c2), e13 = ex2(s1[3] * c2);
            rsum[0][0] += e00 + e01;  rsum[0][1] += e02 + e03;
            rsum[1][0] += e10 + e11;  rsum[1][1] += e12 + e13;
            int kt = nt >> 1, lo = (nt & 1) * 2;
            pf[0][kt][lo + 0] = pack_bf16x2(e00, e01);
            pf[0][kt][lo + 1] = pack_bf16x2(e02, e03);
            pf[1][kt][lo + 0] = pack_bf16x2(e10, e11);
            pf[1][kt][lo + 1] = pack_bf16x2(e12, e13);
        }
#pragma unroll
        for (int kt = 0; kt < 4; kt++) {
            u32 v0, v1, v2, v3;
            u32 addr = (u32)__cvta_generic_to_shared(
                Vc + (kt * 16 + (g & 1) * 8 + i) * AST + (g >> 1) * 8);
            ldsm_x4_t(v0, v1, v2, v3, addr);
            u32 b0[2] = {v0, v1};
            u32 b1[2] = {v2, v3};
            mma_bf16(o[0][0], pf[0][kt], b0);
            mma_bf16(o[0][1], pf[0][kt], b1);
            mma_bf16(o[1][0], pf[1][kt], b0);
            mma_bf16(o[1][1], pf[1][kt], b1);
        }
    }

#pragma unroll
    for (int mt = 0; mt < 2; mt++)
#pragma unroll
        for (int hh = 0; hh < 2; hh++) {
            float v = rsum[mt][hh];
            v += __shfl_xor_sync(0xffffffffu, v, 1);
            v += __shfl_xor_sync(0xffffffffu, v, 2);
            rsum[mt][hh] = v;
        }
}

// =================================================================
// Merged attention: blk<2048 window, else grid. 256 thr.
// =================================================================
__global__ __launch_bounds__(256) void attn_kernel(
    const __nv_bfloat16* __restrict__ qkv, __nv_bfloat16* __restrict__ abuf)
{
    __shared__ __align__(16) __nv_bfloat16 Qs[256 * AST];
    __shared__ __align__(16) __nv_bfloat16 Ks[256 * AST];
    __shared__ __align__(16) __nv_bfloat16 Vs[256 * AST];

    int blk = blockIdx.x;
    int tid = threadIdx.x;
    int wrp = tid >> 5, lane = tid & 31;
    int r4 = lane >> 2, c4 = lane & 3;

    if (blk < 2048) {
        int b  = blk >> 8;
        int wy = (blk >> 4) & 15;
        int wx = blk & 15;
        {
            int h = tid >> 6, t = tid & 63;
            int y = t >> 3, x = t & 7;
            size_t p = (size_t)(wy * 8 + y) * WW + wx * 8 + x;
            const __nv_bfloat16* base = qkv + ((size_t)b * P + p) * 384 + h * 16;
            int row = (h * 64 + t) * AST;
            const uint4* q4 = (const uint4*)base;
            const uint4* k4 = (const uint4*)(base + 128);
            const uint4* v4 = (const uint4*)(base + 256);
            *(uint4*)&Qs[row] = q4[0];  *(uint4*)&Qs[row + 8] = q4[1];
            *(uint4*)&Ks[row] = k4[0];  *(uint4*)&Ks[row + 8] = k4[1];
            *(uint4*)&Vs[row] = v4[0];  *(uint4*)&Vs[row + 8] = v4[1];
        }
        __syncthreads();

        int h = wrp >> 1;
        int qb = (wrp & 1) * 32;
        float o[2][2][4], rsum[2][2];
        attn_warp(Qs + (h * 64 + qb) * AST, Ks + h * 64 * AST, Vs + h * 64 * AST,
                  1, lane, o, rsum);

#pragma unroll
        for (int mt = 0; mt < 2; mt++) {
            float inv0 = 1.f / rsum[mt][0];
            float inv1 = 1.f / rsum[mt][1];
#pragma unroll
            for (int hh = 0; hh < 2; hh++) {
                int q = qb + mt * 16 + hh * 8 + r4;
                size_t p = (size_t)(wy * 8 + (q >> 3)) * WW + wx * 8 + (q & 7);
                float inv = hh ? inv1 : inv0;
                __nv_bfloat16* ob = abuf + ((size_t)b * P + p) * C + h * 16;
#pragma unroll
                for (int nh = 0; nh < 2; nh++) {
                    float ox = o[mt][nh][hh * 2]     * inv;
                    float oy = o[mt][nh][hh * 2 + 1] * inv;
                    *(__nv_bfloat162*)(ob + nh * 8 + c4 * 2) =
                        __floats2bfloat162_rn(ox, oy);
                }
            }
        }
    } else {
        int gb  = blk - 2048;
        int b   = gb >> 8;
        int pos = (gb >> 2) & 63;
        int hg  = gb & 3;
        int y = pos >> 3, x = pos & 7;
        {
            int j = tid;
            int wy = j >> 4, wx = j & 15;
            size_t p = (size_t)(wy * 8 + y) * WW + wx * 8 + x;
            const __nv_bfloat16* base = qkv + ((size_t)b * P + p) * 384 + 64 + hg * 16;
            int row = j * AST;
            const uint4* q4 = (const uint4*)base;
            const uint4* k4 = (const uint4*)(base + 128);
            const uint4* v4 = (const uint4*)(base + 256);
            *(uint4*)&Qs[row] = q4[0];  *(uint4*)&Qs[row + 8] = q4[1];
            *(uint4*)&Ks[row] = k4[0];  *(uint4*)&Ks[row + 8] = k4[1];
            *(uint4*)&Vs[row] = v4[0];  *(uint4*)&Vs[row + 8] = v4[1];
        }
        __syncthreads();

        int qb = wrp * 32;
        float o[2][2][4], rsum[2][2];
        attn_warp(Qs + qb * AST, Ks, Vs, 4, lane, o, rsum);

#pragma unroll
        for (int mt = 0; mt < 2; mt++) {
            float inv0 = 1.f / rsum[mt][0];
            float inv1 = 1.f / rsum[mt][1];
#pragma unroll
            for (int hh = 0; hh < 2; hh++) {
                int j = qb + mt * 16 + hh * 8 + r4;
                int wy = j >> 4, wx = j & 15;
                size_t p = (size_t)(wy * 8 + y) * WW + wx * 8 + x;
                float inv = hh ? inv1 : inv0;
                __nv_bfloat16* ob = abuf + ((size_t)b * P + p) * C + 64 + hg * 16;
#pragma unroll
                for (int nh = 0; nh < 2; nh++) {
                    float ox = o[mt][nh][hh * 2]     * inv;
                    float oy = o[mt][nh][hh * 2 + 1] * inv;
                    *(__nv_bfloat162*)(ob + nh * 8 + c4 * 2) =
                        __floats2bfloat162_rn(ox, oy);
                }
            }
        }
    }
}

// =================================================================
// host launcher
// =================================================================
extern "C" void kernel_launch(void* const* d_in, const int* in_sizes, int n_in,
                              void* d_out, int out_size)
{
    const float* x       = (const float*)d_in[0];
    const float* conv_w  = (const float*)d_in[1];
    const float* conv_b  = (const float*)d_in[2];
    const float* norm1_w = (const float*)d_in[3];
    const float* norm1_b = (const float*)d_in[4];
    const float* wqkv    = (const float*)d_in[5];
    const float* proj_w  = (const float*)d_in[6];
    const float* proj_b  = (const float*)d_in[7];
    const float* norm2_w = (const float*)d_in[8];
    const float* norm2_b = (const float*)d_in[9];
    const float* fc1_w   = (const float*)d_in[10];
    const float* fc1_b   = (const float*)d_in[11];
    const float* fc2_w   = (const float*)d_in[12];
    const float* fc2_b   = (const float*)d_in[13];
    const float* ls1     = (const float*)d_in[14];
    const float* ls2     = (const float*)d_in[15];
    float* out = (float*)d_out;

    float *pxt, *pxt2;
    __nv_bfloat16 *pqkv, *pabuf, *ph, *pwq, *pwp, *pw1, *pw2;
    cudaGetSymbolAddress((void**)&pxt,   g_xt);
    cudaGetSymbolAddress((void**)&pqkv,  g_qkvb);
    cudaGetSymbolAddress((void**)&pabuf, g_abuf);
    cudaGetSymbolAddress((void**)&pxt2,  g_xt2);
    cudaGetSymbolAddress((void**)&ph,    g_h);
    cudaGetSymbolAddress((void**)&pwq,   g_wqkv_t);
    cudaGetSymbolAddress((void**)&pwp,   g_proj_t);
    cudaGetSymbolAddress((void**)&pw1,   g_fc1_t);
    cudaGetSymbolAddress((void**)&pw2,   g_fc2_t);

    // 0. weight prep
    wt_all_kernel<<<192, dim3(32, 8)>>>(wqkv, proj_w, fc1_w, fc2_w,
                                        pwq, pwp, pw1, pw2);

    // 1. conv + residual + transpose -> xt
    conv_kernel<<<dim3(16, HH, BS), 256>>>(x, conv_w, conv_b, pxt);

    // 2. LN1 + QKV GEMM fused
    {
        EpiQKVb e{pqkv};
        lngemm_kernel<3, EpiQKVb><<<(unsigned)(M / 128), 256>>>(
            pxt, norm1_w, norm1_b, pwq, e);
    }

    // 3. merged attention
    attn_kernel<<<2 * BS * 256, 256>>>(pqkv, pabuf);

    // 4. FUSED proj + ls1-residual + LN2 + FC1(+GELU)
    projln_fc1_kernel<<<(unsigned)(M / 128), 256>>>(
        pabuf, pwp, proj_b, ls1, pxt, pxt2,
        norm2_w, norm2_b, pw1, fc1_b, ph);

    // 5. FC2 + bias + ls2 + residual + transposed store -> d_out
    bgemm_fc2_tr_kernel<<<dim3(1, (unsigned)(M / 128)), 256>>>(
        ph, pw2, fc2_b, ls2, pxt2, out);

    (void)in_sizes; (void)n_in; (void)out_size;
}